// round 1
// baseline (speedup 1.0000x reference)
#include <cuda_runtime.h>

// STN_51771535785990: separable bilinear grid_sample with diagonal affine,
// x: [32, 3, 512, 512] float32, scale_factors: [2] float32 (on device).
// out: [32, 3, 512, 512] float32.
//
// One-pass gather: each thread computes 4 consecutive output pixels (one
// float4 store). Per-pixel it evaluates the affine_grid -> grid_sample
// coordinate math exactly as the reference:
//   ix = 0.5 * (sx*(2x+1-W) + (W-1)),  4-tap bilinear, zeros padding.

#define B_ 32
#define C_ 3
#define H_ 512
#define W_ 512
#define PLANES (B_ * C_)      // 96
#define PLANE_ELEMS (H_ * W_) // 262144

__global__ __launch_bounds__(256) void stn_bilinear_kernel(
    const float* __restrict__ in,
    const float* __restrict__ sf,
    float* __restrict__ out)
{
    const int W4 = W_ / 4; // float4 groups per row
    int idx = blockIdx.x * blockDim.x + threadIdx.x; // float4 index
    // total float4s = PLANES * H_ * W4 = 96*512*128 = 6,291,456
    if (idx >= PLANES * H_ * W4) return;

    int x4 = idx % W4;
    int t  = idx / W4;
    int y  = t % H_;
    int p  = t / H_;

    float sx = __ldg(sf + 0);
    float sy = __ldg(sf + 1);

    // ----- vertical (row) coordinate: shared by all 4 pixels -----
    float iy   = 0.5f * (sy * (2.0f * (float)y + 1.0f - (float)H_) + (float)(H_ - 1));
    float iy0f = floorf(iy);
    float wy1  = iy - iy0f;
    float wy0  = 1.0f - wy1;
    int   iy0  = (int)iy0f;
    int   iy1  = iy0 + 1;
    float vy0  = (iy0 >= 0 && iy0 < H_) ? 1.0f : 0.0f;
    float vy1  = (iy1 >= 0 && iy1 < H_) ? 1.0f : 0.0f;
    int   iy0c = min(max(iy0, 0), H_ - 1);
    int   iy1c = min(max(iy1, 0), H_ - 1);
    float cy0  = wy0 * vy0;
    float cy1  = wy1 * vy1;

    const float* row0 = in + (size_t)p * PLANE_ELEMS + (size_t)iy0c * W_;
    const float* row1 = in + (size_t)p * PLANE_ELEMS + (size_t)iy1c * W_;

    float r[4];
#pragma unroll
    for (int j = 0; j < 4; ++j) {
        int   xo   = x4 * 4 + j;
        float ix   = 0.5f * (sx * (2.0f * (float)xo + 1.0f - (float)W_) + (float)(W_ - 1));
        float ix0f = floorf(ix);
        float wx1  = ix - ix0f;
        float wx0  = 1.0f - wx1;
        int   ix0  = (int)ix0f;
        int   ix1  = ix0 + 1;
        float vx0  = (ix0 >= 0 && ix0 < W_) ? 1.0f : 0.0f;
        float vx1  = (ix1 >= 0 && ix1 < W_) ? 1.0f : 0.0f;
        int   ix0c = min(max(ix0, 0), W_ - 1);
        int   ix1c = min(max(ix1, 0), W_ - 1);
        float cx0  = wx0 * vx0;
        float cx1  = wx1 * vx1;

        float top = cx0 * __ldg(row0 + ix0c) + cx1 * __ldg(row0 + ix1c);
        float bot = cx0 * __ldg(row1 + ix0c) + cx1 * __ldg(row1 + ix1c);
        r[j] = cy0 * top + cy1 * bot;
    }

    float4 v = make_float4(r[0], r[1], r[2], r[3]);
    reinterpret_cast<float4*>(out)[idx] = v;
}

extern "C" void kernel_launch(void* const* d_in, const int* in_sizes, int n_in,
                              void* d_out, int out_size)
{
    const float* x  = (const float*)d_in[0];
    const float* sf = (const float*)d_in[1];
    float* out      = (float*)d_out;

    const int total4 = PLANES * H_ * (W_ / 4); // 6,291,456
    const int threads = 256;
    const int blocks = (total4 + threads - 1) / threads; // 24576
    stn_bilinear_kernel<<<blocks, threads>>>(x, sf, out);
}

// round 2
// speedup vs baseline: 1.7035x; 1.7035x over previous
#include <cuda_runtime.h>

// STN_51771535785990: separable bilinear grid_sample with diagonal affine,
// x: [32, 3, 512, 512] float32, scale_factors: [2] float32 (device-resident).
// out: [32, 3, 512, 512] float32.
//
// Two paths, selected at runtime from the device-resident scale factors
// (warp-uniform branch, graph-capture safe, no host readback):
//   * sx==1 && sy==1  ->  the sampling grid is exactly the identity
//     (ix = 0.5*((2x+1-W) + (W-1)) = x, exact in fp32), so the op is a
//     bit-exact copy. Vectorized float4 copy with 4-deep MLP.
//   * generic         ->  4-tap bilinear gather (reference-exact math).

#define B_ 32
#define C_ 3
#define H_ 512
#define W_ 512
#define PLANES (B_ * C_)      // 96
#define PLANE_ELEMS (H_ * W_) // 262144
#define W4 (W_ / 4)           // 128 float4 groups per row
#define TOTAL4 (PLANES * H_ * W4)  // 6,291,456 float4s
#define THREADS 256
#define BLOCKS 6144
#define STRIDE4 (BLOCKS * THREADS) // 1,572,864 ; TOTAL4 = 4 * STRIDE4 exactly

__device__ __forceinline__ float4 sample_group(
    const float* __restrict__ in, int idx4, float sx, float sy)
{
    int x4 = idx4 % W4;
    int t  = idx4 / W4;
    int y  = t % H_;
    int p  = t / H_;

    // vertical coordinate, shared by the 4 pixels of this group
    float iy   = 0.5f * (sy * (2.0f * (float)y + 1.0f - (float)H_) + (float)(H_ - 1));
    float iy0f = floorf(iy);
    float wy1  = iy - iy0f;
    float wy0  = 1.0f - wy1;
    int   iy0  = (int)iy0f;
    int   iy1  = iy0 + 1;
    float vy0  = (iy0 >= 0 && iy0 < H_) ? 1.0f : 0.0f;
    float vy1  = (iy1 >= 0 && iy1 < H_) ? 1.0f : 0.0f;
    int   iy0c = min(max(iy0, 0), H_ - 1);
    int   iy1c = min(max(iy1, 0), H_ - 1);
    float cy0  = wy0 * vy0;
    float cy1  = wy1 * vy1;

    const float* row0 = in + (size_t)p * PLANE_ELEMS + (size_t)iy0c * W_;
    const float* row1 = in + (size_t)p * PLANE_ELEMS + (size_t)iy1c * W_;

    float r[4];
#pragma unroll
    for (int j = 0; j < 4; ++j) {
        int   xo   = x4 * 4 + j;
        float ix   = 0.5f * (sx * (2.0f * (float)xo + 1.0f - (float)W_) + (float)(W_ - 1));
        float ix0f = floorf(ix);
        float wx1  = ix - ix0f;
        float wx0  = 1.0f - wx1;
        int   ix0  = (int)ix0f;
        int   ix1  = ix0 + 1;
        float vx0  = (ix0 >= 0 && ix0 < W_) ? 1.0f : 0.0f;
        float vx1  = (ix1 >= 0 && ix1 < W_) ? 1.0f : 0.0f;
        int   ix0c = min(max(ix0, 0), W_ - 1);
        int   ix1c = min(max(ix1, 0), W_ - 1);
        float cx0  = wx0 * vx0;
        float cx1  = wx1 * vx1;

        float top = cx0 * __ldg(row0 + ix0c) + cx1 * __ldg(row0 + ix1c);
        float bot = cx0 * __ldg(row1 + ix0c) + cx1 * __ldg(row1 + ix1c);
        r[j] = cy0 * top + cy1 * bot;
    }
    return make_float4(r[0], r[1], r[2], r[3]);
}

__global__ __launch_bounds__(THREADS) void stn_kernel(
    const float* __restrict__ in,
    const float* __restrict__ sf,
    float* __restrict__ out)
{
    const int tid = blockIdx.x * blockDim.x + threadIdx.x;
    const float sx = __ldg(sf + 0);
    const float sy = __ldg(sf + 1);

    const float4* __restrict__ in4  = reinterpret_cast<const float4*>(in);
    float4* __restrict__       out4 = reinterpret_cast<float4*>(out);

    if (sx == 1.0f && sy == 1.0f) {
        // identity grid -> bit-exact copy. 4 float4s per thread, loads
        // front-batched for MLP=4.
        float4 v0 = __ldg(in4 + tid + 0 * STRIDE4);
        float4 v1 = __ldg(in4 + tid + 1 * STRIDE4);
        float4 v2 = __ldg(in4 + tid + 2 * STRIDE4);
        float4 v3 = __ldg(in4 + tid + 3 * STRIDE4);
        out4[tid + 0 * STRIDE4] = v0;
        out4[tid + 1 * STRIDE4] = v1;
        out4[tid + 2 * STRIDE4] = v2;
        out4[tid + 3 * STRIDE4] = v3;
    } else {
        // generic bilinear gather, 4 groups of 4 pixels per thread
#pragma unroll
        for (int i = 0; i < 4; ++i) {
            int idx4 = tid + i * STRIDE4;
            out4[idx4] = sample_group(in, idx4, sx, sy);
        }
    }
}

extern "C" void kernel_launch(void* const* d_in, const int* in_sizes, int n_in,
                              void* d_out, int out_size)
{
    const float* x  = (const float*)d_in[0];
    const float* sf = (const float*)d_in[1];
    float* out      = (float*)d_out;

    stn_kernel<<<BLOCKS, THREADS>>>(x, sf, out);
}